// round 5
// baseline (speedup 1.0000x reference)
#include <cuda_runtime.h>
#include <cstdint>

// Problem constants
#define SN 96        // slices (ROW)
#define NB 32        // batch B
#define MM 3072      // SN*NB recurrent rows
#define OLEN 48      // COL (original slice len)
#define SLT 143      // SN + OLEN - 1 time steps
#define HH 128       // hidden
#define DD 32        // input feature dim
#define KK 288       // fused GEMM K = 2H + D
#define NG 768       // gate width = 6H

#define NBLK 128     // persistent blocks (<=148 SMs, single wave)
#define NTHR 512

// SMEM layout (floats): sW[288*96] | sF[192*36] | sB[96]
#define SW_ELEMS (KK * 96)
#define SF_STRIDE 36
#define SF_ELEMS (192 * SF_STRIDE)
#define SMEM_FLOATS (SW_ELEMS + SF_ELEMS + 96)

typedef unsigned long long ull;

// ---------------- device scratch ----------------
__device__ float g_W[KK * NG];      // fused, column-permuted weight [288][768]
__device__ float g_bias[NG];
__device__ float g_hrow[2][MM * HH];
__device__ float g_hcol[2][MM * HH];
__device__ unsigned g_bar;          // monotonic barrier counter

// ---------------- helpers ----------------
__device__ __forceinline__ ull pack2(float x, float y) {
    ull r;
    asm("mov.b64 %0, {%1, %2};" : "=l"(r) : "f"(x), "f"(y));
    return r;
}
__device__ __forceinline__ void unpack2(ull v, float& x, float& y) {
    asm("mov.b64 {%0, %1}, %2;" : "=f"(x), "=f"(y) : "l"(v));
}
__device__ __forceinline__ void fma2(ull& acc, ull a, ull b) {
    asm("fma.rn.f32x2 %0, %1, %2, %0;" : "+l"(acc) : "l"(a), "l"(b));
}
__device__ __forceinline__ float tanh_ap(float x) {
    float y;
    asm("tanh.approx.f32 %0, %1;" : "=f"(y) : "f"(x));
    return y;
}
__device__ __forceinline__ float sigmoid_f(float x) {
    return fmaf(0.5f, tanh_ap(0.5f * x), 0.5f);
}

// ---------------- init ----------------
__global__ void zero_all_kernel() {
    int n = MM * HH;
    for (int i = blockIdx.x * blockDim.x + threadIdx.x; i < n; i += gridDim.x * blockDim.x) {
        g_hrow[0][i] = 0.f; g_hrow[1][i] = 0.f;
        g_hcol[0][i] = 0.f; g_hcol[1][i] = 0.f;
    }
    if (blockIdx.x == 0 && threadIdx.x == 0) g_bar = 0u;
}

// ---------------- prep: fused + permuted weights ----------------
// K layout: [0:128)=h_row, [128:256)=h_col, [256:288)=x
// col permutation: p = u*6 + g, original column oc = g*128 + u
//   g: 0=u_r 1=o_r 2=u_c 3=o_c 4=i_r 5=i_c
__global__ void prep_weights_kernel(
    const float* __restrict__ Wf,  const float* __restrict__ bf,
    const float* __restrict__ Wrm, const float* __restrict__ brm,
    const float* __restrict__ Wcm, const float* __restrict__ bcm,
    const float* __restrict__ Wrxm, const float* __restrict__ brxm,
    const float* __restrict__ Wcxm, const float* __restrict__ bcxm)
{
    int p = blockIdx.x;              // 0..767
    int u = p / 6, g = p % 6;
    int oc = g * 128 + u;

    __shared__ float sWf[KK];
    for (int i = threadIdx.x; i < KK; i += blockDim.x) sWf[i] = Wf[oc * KK + i];
    __syncthreads();

    int k = threadIdx.x;             // 288 threads
    if (k < KK) {
        float acc = 0.f;
        if (k < HH) {
            #pragma unroll 4
            for (int h = 0; h < HH; h++) acc += Wrm[h * HH + k] * sWf[h];
        } else if (k < 2 * HH) {
            int kk = k - HH;
            #pragma unroll 4
            for (int h = 0; h < HH; h++) acc += Wcm[h * HH + kk] * sWf[HH + h];
        } else {
            int d = k - 2 * HH;
            #pragma unroll 4
            for (int h = 0; h < HH; h++)
                acc += Wrxm[h * DD + d] * sWf[h] + Wcxm[h * DD + d] * sWf[HH + h];
            acc += sWf[2 * HH + d];
        }
        g_W[k * NG + p] = acc;
    }
    if (threadIdx.x == 0) {
        float bacc = bf[oc];
        for (int h = 0; h < HH; h++)
            bacc += (brxm[h] + brm[h]) * sWf[h] + (bcxm[h] + bcm[h]) * sWf[HH + h];
        g_bias[p] = bacc;
    }
}

// ---------------- persistent kernel ----------------
// 128 blocks x 512 threads. Block b: nTile = b&7 (96 cols = 16 units),
// mTile = b>>3 (192 rows = 6 slices). Thread (ct=tid&15, rt=tid>>4):
// 6 rows x 1 unit (6 permuted gate columns).
__global__ __launch_bounds__(NTHR, 1) void persist_kernel(
    const float* __restrict__ input, float* __restrict__ out, int write_hidden)
{
    extern __shared__ float smem[];
    float* sW = smem;                 // [288][96]
    float* sF = smem + SW_ELEMS;      // [192][36]
    float* sB = sF + SF_ELEMS;        // [96]

    const int tid   = threadIdx.x;
    const int ct    = tid & 15;
    const int rt    = tid >> 4;
    const int nTile = blockIdx.x & 7;
    const int mTile = blockIdx.x >> 3;
    const int mBase = mTile * 192;
    const int nBase = nTile * 96;
    const int myRow = rt * 6;
    const int U     = nTile * 16 + ct;       // global hidden unit 0..127

    // ---- one-time: stage weight slab + bias into SMEM ----
    for (int lin = tid; lin < KK * 24; lin += NTHR) {
        int k = lin / 24, j4 = lin % 24;
        float4 w = *reinterpret_cast<const float4*>(&g_W[k * NG + nBase + j4 * 4]);
        *reinterpret_cast<float4*>(&sW[k * 96 + j4 * 4]) = w;
    }
    if (tid < 96) sB[tid] = g_bias[nBase + tid];
    __syncthreads();

    float bloc[6];
    #pragma unroll
    for (int j = 0; j < 6; j++) bloc[j] = sB[ct * 6 + j];

    const long long HR_BASE = (long long)MM * SLT * 256;
    const long long HC_BASE = HR_BASE + (long long)NB * SN * HH;

    for (int t = 0; t < SLT; ++t) {
        const int pin = t & 1;
        const float* __restrict__ hrow_in = g_hrow[pin];
        const float* __restrict__ hcol_in = g_hcol[pin];
        float* __restrict__ hrow_out = g_hrow[pin ^ 1];
        float* __restrict__ hcol_out = g_hcol[pin ^ 1];

        // whole block strictly pre-start -> all 192 rows share one trajectory
        const bool dup = (mTile * 6 > t);

        ull acc[6][3];
        #pragma unroll
        for (int i = 0; i < 6; i++)
            #pragma unroll
            for (int j = 0; j < 3; j++) acc[i][j] = 0ull;

        for (int kc = 0; kc < 9; ++kc) {
            // ---- load feature chunk (192 rows x 32 k) straight into sF ----
            #pragma unroll
            for (int it = 0; it < 12; ++it) {
                int lin = tid + it * NTHR;
                int row = lin >> 5, k = lin & 31;
                int m = mBase + row;
                float v;
                if (kc < 4) {
                    v = __ldcg(&hrow_in[m * HH + kc * 32 + k]);
                } else if (kc < 8) {
                    v = __ldcg(&hcol_in[m * HH + (kc - 4) * 32 + k]);
                } else {
                    int r = m >> 5, b = m & 31;
                    int c = t - r;
                    v = (c >= 0 && c < OLEN)
                        ? __ldg(&input[((b * SN + r) * OLEN + c) * DD + k])
                        : 0.f;
                }
                sF[row * SF_STRIDE + k] = v;
            }
            __syncthreads();

            // ---- compute 32 k-values of this chunk ----
            const float* wbase = &sW[kc * 32 * 96 + ct * 6];
            if (!dup) {
                #pragma unroll
                for (int k4 = 0; k4 < 8; ++k4) {
                    float4 f[6];
                    #pragma unroll
                    for (int i = 0; i < 6; i++)
                        f[i] = *reinterpret_cast<const float4*>(&sF[(myRow + i) * SF_STRIDE + k4 * 4]);
                    #pragma unroll
                    for (int kk = 0; kk < 4; ++kk) {
                        const ull* wp = reinterpret_cast<const ull*>(wbase + (k4 * 4 + kk) * 96);
                        ull w0 = wp[0], w1 = wp[1], w2 = wp[2];
                        #pragma unroll
                        for (int i = 0; i < 6; i++) {
                            float fv = (&f[i].x)[kk];
                            ull ff = pack2(fv, fv);
                            fma2(acc[i][0], ff, w0);
                            fma2(acc[i][1], ff, w1);
                            fma2(acc[i][2], ff, w2);
                        }
                    }
                }
            } else {
                // all rows identical: compute one row only
                #pragma unroll
                for (int k4 = 0; k4 < 8; ++k4) {
                    float4 f0 = *reinterpret_cast<const float4*>(&sF[myRow * SF_STRIDE + k4 * 4]);
                    #pragma unroll
                    for (int kk = 0; kk < 4; ++kk) {
                        const ull* wp = reinterpret_cast<const ull*>(wbase + (k4 * 4 + kk) * 96);
                        ull w0 = wp[0], w1 = wp[1], w2 = wp[2];
                        float fv = (&f0.x)[kk];
                        ull ff = pack2(fv, fv);
                        fma2(acc[0][0], ff, w0);
                        fma2(acc[0][1], ff, w1);
                        fma2(acc[0][2], ff, w2);
                    }
                }
            }
            __syncthreads();
        }

        // ---- epilogue: bias + gating + state update + outputs ----
        const int nrows = dup ? 1 : 6;
        for (int i = 0; i < nrows; i++) {
            int m = mBase + myRow + i;
            int r = m >> 5, b = m & 31;

            float a_ur, a_or, a_uc, a_oc, a_ir, a_ic;
            unpack2(acc[i][0], a_ur, a_or);
            unpack2(acc[i][1], a_uc, a_oc);
            unpack2(acc[i][2], a_ir, a_ic);
            a_ur += bloc[0]; a_or += bloc[1];
            a_uc += bloc[2]; a_oc += bloc[3];
            a_ir += bloc[4]; a_ic += bloc[5];

            float hr = __ldcg(&hrow_in[m * HH + U]);
            float hc = __ldcg(&hcol_in[m * HH + U]);

            float ur = sigmoid_f(a_ur);
            float og = sigmoid_f(a_or);
            float uc = sigmoid_f(a_uc);
            float oc = sigmoid_f(a_oc);
            float ir = tanh_ap(a_ir);
            float ic = tanh_ap(a_ic);

            float hrn = tanh_ap((1.f - ur) * hr + ur * ir) * og;
            float hcn = tanh_ap((1.f - uc) * hc + uc * ic) * oc;

            if (!dup) {
                long long ob = ((long long)m * SLT + t) * 256;
                out[ob + U]       = hrn;
                out[ob + 128 + U] = hcn;

                hrow_out[m * HH + U] = hrn;
                int ms = m + NB; if (ms >= MM) ms -= MM;   // roll(h_col, B)
                hcol_out[ms * HH + U] = hcn;

                if (write_hidden) {
                    if (t - r == OLEN - 1)
                        out[HR_BASE + ((long long)b * SN + r) * HH + U] = hrn;
                    if (r == SN - 1 && t >= SN - 1)
                        out[HC_BASE + ((long long)b * OLEN + (t - (SN - 1))) * HH + U] = hcn;
                }
            } else {
                // replicate identical result to all 6 rows of this thread
                #pragma unroll
                for (int ii = 0; ii < 6; ii++) {
                    int mr = mBase + myRow + ii;
                    long long ob = ((long long)mr * SLT + t) * 256;
                    out[ob + U]       = hrn;
                    out[ob + 128 + U] = hcn;
                    hrow_out[mr * HH + U] = hrn;
                    int ms = mr + NB; if (ms >= MM) ms -= MM;
                    hcol_out[ms * HH + U] = hcn;
                }
                // hidden picks never fire for pre-start rows
            }
        }

        // ---- software grid barrier (all 128 blocks resident, single wave) ----
        __threadfence();                       // release state writes (gpu scope)
        __syncthreads();
        if (tid == 0) {
            atomicAdd(&g_bar, 1u);
            unsigned target = (unsigned)NBLK * (unsigned)(t + 1);
            unsigned v;
            do {
                asm volatile("ld.global.acquire.gpu.u32 %0, [%1];" : "=r"(v) : "l"(&g_bar));
            } while (v < target);
        }
        __syncthreads();
    }
}

// ---------------- launch ----------------
extern "C" void kernel_launch(void* const* d_in, const int* in_sizes, int n_in,
                              void* d_out, int out_size) {
    const float* input = (const float*)d_in[0];
    const float* Wf    = (const float*)d_in[1];
    const float* bf    = (const float*)d_in[2];
    const float* Wrm   = (const float*)d_in[3];
    const float* brm   = (const float*)d_in[4];
    const float* Wcm   = (const float*)d_in[5];
    const float* bcm   = (const float*)d_in[6];
    const float* Wrxm  = (const float*)d_in[7];
    const float* brxm  = (const float*)d_in[8];
    const float* Wcxm  = (const float*)d_in[9];
    const float* bcxm  = (const float*)d_in[10];
    float* out = (float*)d_out;

    long long need = (long long)MM * SLT * 256 + (long long)NB * SN * HH + (long long)NB * OLEN * HH;
    int write_hidden = ((long long)out_size >= need) ? 1 : 0;

    size_t smem_bytes = (size_t)SMEM_FLOATS * sizeof(float);  // ~135 KB
    cudaFuncSetAttribute(persist_kernel, cudaFuncAttributeMaxDynamicSharedMemorySize,
                         (int)smem_bytes);

    zero_all_kernel<<<256, 256>>>();
    prep_weights_kernel<<<NG, KK>>>(Wf, bf, Wrm, brm, Wcm, bcm, Wrxm, brxm, Wcxm, bcxm);
    persist_kernel<<<NBLK, NTHR, smem_bytes>>>(input, out, write_hidden);
}

// round 6
// speedup vs baseline: 1.0404x; 1.0404x over previous
#include <cuda_runtime.h>
#include <cstdint>

// Problem constants
#define SN 96        // slices (ROW)
#define NB 32        // batch B
#define MM 3072      // SN*NB recurrent rows
#define OLEN 48      // COL (original slice len)
#define SLT 143      // SN + OLEN - 1 time steps
#define HH 128       // hidden
#define DD 32        // input feature dim
#define KK 288       // fused GEMM K = 2H + D
#define NG 768       // gate width = 6H

typedef unsigned long long ull;

// ---------------- device scratch ----------------
__device__ float g_W[KK * NG];      // fused, column-permuted weight [288][768]
__device__ float g_bias[NG];
__device__ float g_hrow[2][MM * HH];
__device__ float g_hcol[2][MM * HH];

// ---------------- helpers ----------------
__device__ __forceinline__ ull pack2(float x, float y) {
    ull r;
    asm("mov.b64 %0, {%1, %2};" : "=l"(r) : "f"(x), "f"(y));
    return r;
}
__device__ __forceinline__ void unpack2(ull v, float& x, float& y) {
    asm("mov.b64 {%0, %1}, %2;" : "=f"(x), "=f"(y) : "l"(v));
}
__device__ __forceinline__ void fma2(ull& acc, ull a, ull b) {
    asm("fma.rn.f32x2 %0, %1, %2, %0;" : "+l"(acc) : "l"(a), "l"(b));
}
__device__ __forceinline__ float tanh_ap(float x) {
    float y;
    asm("tanh.approx.f32 %0, %1;" : "=f"(y) : "f"(x));
    return y;
}
__device__ __forceinline__ float sigmoid_f(float x) {
    return fmaf(0.5f, tanh_ap(0.5f * x), 0.5f);
}

// ---------------- init ----------------
__global__ void zero_all_kernel() {
    int n = MM * HH;
    for (int i = blockIdx.x * blockDim.x + threadIdx.x; i < n; i += gridDim.x * blockDim.x) {
        g_hrow[0][i] = 0.f; g_hrow[1][i] = 0.f;
        g_hcol[0][i] = 0.f; g_hcol[1][i] = 0.f;
    }
}

// ---------------- prep: fused + permuted weights ----------------
// K layout: [0:128)=h_row, [128:256)=h_col, [256:288)=x
// col permutation: p = u*6 + g, original column oc = g*128 + u
//   g: 0=u_r 1=o_r 2=u_c 3=o_c 4=i_r 5=i_c
__global__ void prep_weights_kernel(
    const float* __restrict__ Wf,  const float* __restrict__ bf,
    const float* __restrict__ Wrm, const float* __restrict__ brm,
    const float* __restrict__ Wcm, const float* __restrict__ bcm,
    const float* __restrict__ Wrxm, const float* __restrict__ brxm,
    const float* __restrict__ Wcxm, const float* __restrict__ bcxm)
{
    int p = blockIdx.x;              // 0..767
    int u = p / 6, g = p % 6;
    int oc = g * 128 + u;

    __shared__ float sWf[KK];
    for (int i = threadIdx.x; i < KK; i += blockDim.x) sWf[i] = Wf[oc * KK + i];
    __syncthreads();

    int k = threadIdx.x;             // 288 threads
    if (k < KK) {
        float acc = 0.f;
        if (k < HH) {
            #pragma unroll 4
            for (int h = 0; h < HH; h++) acc += Wrm[h * HH + k] * sWf[h];
        } else if (k < 2 * HH) {
            int kk = k - HH;
            #pragma unroll 4
            for (int h = 0; h < HH; h++) acc += Wcm[h * HH + kk] * sWf[HH + h];
        } else {
            int d = k - 2 * HH;
            #pragma unroll 4
            for (int h = 0; h < HH; h++)
                acc += Wrxm[h * DD + d] * sWf[h] + Wcxm[h * DD + d] * sWf[HH + h];
            acc += sWf[2 * HH + d];
        }
        g_W[k * NG + p] = acc;
    }
    if (threadIdx.x == 0) {
        float bacc = bf[oc];
        for (int h = 0; h < HH; h++)
            bacc += (brxm[h] + brm[h]) * sWf[h] + (bcxm[h] + bcm[h]) * sWf[HH + h];
        g_bias[p] = bacc;
    }
}

// ---------------- per-step fused GEMM + gating ----------------
// grid: (8 n-tiles of 96, 48 m-tiles of 64), 256 threads.
// Thread (ct=tid&15, rt=tid>>4): 4 rows x 6 cols (= 1 hidden unit's 6 permuted gates).
#define SF2S 34   // sF2 row stride in ull (even -> 16B-aligned k-pair reads)
__global__ __launch_bounds__(256, 3) void step_kernel(
    const float* __restrict__ input,   // [B, SN, OLEN, D]
    float* __restrict__ out,
    int t, int pin, int write_hidden)
{
    __shared__ __align__(16) ull   sF2[64 * SF2S];   // features, (v,v) duplicated
    __shared__ __align__(16) float sW[32 * 96];      // weight chunk [k][col]

    const float* __restrict__ hrow_in = g_hrow[pin];
    const float* __restrict__ hcol_in = g_hcol[pin];
    float* __restrict__ hrow_out = g_hrow[pin ^ 1];
    float* __restrict__ hcol_out = g_hcol[pin ^ 1];

    const int tid    = threadIdx.x;
    const int ct     = tid & 15;
    const int rt     = tid >> 4;
    const int mBase  = blockIdx.y * 64;
    const int nBase  = blockIdx.x * 96;
    const int myRow  = rt * 4;
    const int ct6    = ct * 6;
    const int U      = blockIdx.x * 16 + ct;   // global hidden unit 0..127

    // both slices of this block strictly pre-start -> all 64 rows share one state
    const bool dup = ((mBase >> 5) > t);

    ull acc[4][3];
    #pragma unroll
    for (int i = 0; i < 4; i++)
        #pragma unroll
        for (int j = 0; j < 3; j++) acc[i][j] = 0ull;

    for (int kc = 0; kc < 9; ++kc) {
        // ---- load feature chunk into sF2 as duplicated pairs ----
        if (!dup) {
            #pragma unroll
            for (int it = 0; it < 8; ++it) {
                int lin = tid + it * 256;        // 0..2047
                int row = lin >> 5, k = lin & 31;
                int m = mBase + row;
                float v;
                if (kc < 4) {
                    v = __ldcg(&hrow_in[m * HH + kc * 32 + k]);
                } else if (kc < 8) {
                    v = __ldcg(&hcol_in[m * HH + (kc - 4) * 32 + k]);
                } else {
                    int r = m >> 5, b = m & 31;
                    int c = t - r;
                    v = (c >= 0 && c < OLEN)
                        ? __ldg(&input[((b * SN + r) * OLEN + c) * DD + k])
                        : 0.f;
                }
                sF2[row * SF2S + k] = pack2(v, v);
            }
        } else if (tid < 32) {
            // universal pre-start trajectory: only row 0 needed
            int k = tid;
            float v;
            if (kc < 4)      v = __ldcg(&hrow_in[mBase * HH + kc * 32 + k]);
            else if (kc < 8) v = __ldcg(&hcol_in[mBase * HH + (kc - 4) * 32 + k]);
            else             v = 0.f;   // pre-start always has x = 0
            sF2[k] = pack2(v, v);
        }
        // ---- load weight chunk (32 k x 96 cols) as float4 ----
        #pragma unroll
        for (int it = 0; it < 3; ++it) {
            int lin = tid + it * 256;     // 0..767 float4 slots
            int k   = lin / 24;
            int j4  = lin % 24;
            float4 w = *reinterpret_cast<const float4*>(&g_W[(kc * 32 + k) * NG + nBase + j4 * 4]);
            *reinterpret_cast<float4*>(&sW[k * 96 + j4 * 4]) = w;
        }
        __syncthreads();

        // ---- compute 32 k-values, two at a time ----
        if (!dup) {
            #pragma unroll 4
            for (int k2 = 0; k2 < 16; ++k2) {
                ulonglong2 fp[4];
                #pragma unroll
                for (int i = 0; i < 4; i++)
                    fp[i] = *reinterpret_cast<const ulonglong2*>(&sF2[(myRow + i) * SF2S + 2 * k2]);
                #pragma unroll
                for (int kk = 0; kk < 2; ++kk) {
                    const ull* wp = reinterpret_cast<const ull*>(&sW[(2 * k2 + kk) * 96 + ct6]);
                    ull w0 = wp[0], w1 = wp[1], w2 = wp[2];
                    #pragma unroll
                    for (int i = 0; i < 4; i++) {
                        ull ff = kk ? fp[i].y : fp[i].x;
                        fma2(acc[i][0], ff, w0);
                        fma2(acc[i][1], ff, w1);
                        fma2(acc[i][2], ff, w2);
                    }
                }
            }
        } else {
            #pragma unroll 4
            for (int k2 = 0; k2 < 16; ++k2) {
                ulonglong2 fp = *reinterpret_cast<const ulonglong2*>(&sF2[2 * k2]);
                #pragma unroll
                for (int kk = 0; kk < 2; ++kk) {
                    const ull* wp = reinterpret_cast<const ull*>(&sW[(2 * k2 + kk) * 96 + ct6]);
                    ull w0 = wp[0], w1 = wp[1], w2 = wp[2];
                    ull ff = kk ? fp.y : fp.x;
                    fma2(acc[0][0], ff, w0);
                    fma2(acc[0][1], ff, w1);
                    fma2(acc[0][2], ff, w2);
                }
            }
        }
        __syncthreads();
    }

    // ---- epilogue: bias + gating + state update + outputs ----
    float bloc[6];
    #pragma unroll
    for (int j = 0; j < 6; j++) bloc[j] = g_bias[nBase + ct6 + j];

    const long long HR_BASE = (long long)MM * SLT * 256;
    const long long HC_BASE = HR_BASE + (long long)NB * SN * HH;

    const int nrows = dup ? 1 : 4;

    for (int i = 0; i < nrows; i++) {
        int m = mBase + myRow + i;
        if (dup) m = mBase;           // universal row: state from row 0
        int r = m >> 5, b = m & 31;

        float a_ur, a_or, a_uc, a_oc, a_ir, a_ic;
        unpack2(acc[i][0], a_ur, a_or);
        unpack2(acc[i][1], a_uc, a_oc);
        unpack2(acc[i][2], a_ir, a_ic);
        a_ur += bloc[0]; a_or += bloc[1];
        a_uc += bloc[2]; a_oc += bloc[3];
        a_ir += bloc[4]; a_ic += bloc[5];

        float hr = __ldcg(&hrow_in[m * HH + U]);
        float hc = __ldcg(&hcol_in[m * HH + U]);

        float ur = sigmoid_f(a_ur);
        float og = sigmoid_f(a_or);
        float uc = sigmoid_f(a_uc);
        float oc = sigmoid_f(a_oc);
        float ir = tanh_ap(a_ir);
        float ic = tanh_ap(a_ic);

        float hrn = tanh_ap((1.f - ur) * hr + ur * ir) * og;
        float hcn = tanh_ap((1.f - uc) * hc + uc * ic) * oc;

        if (!dup) {
            long long ob = ((long long)m * SLT + t) * 256;
            out[ob + U]       = hrn;
            out[ob + 128 + U] = hcn;

            hrow_out[m * HH + U] = hrn;
            int ms = m + NB; if (ms >= MM) ms -= MM;   // roll(h_col, B)
            hcol_out[ms * HH + U] = hcn;

            if (write_hidden) {
                if (t - r == OLEN - 1)
                    out[HR_BASE + ((long long)b * SN + r) * HH + U] = hrn;
                if (r == SN - 1 && t >= SN - 1)
                    out[HC_BASE + ((long long)b * OLEN + (t - (SN - 1))) * HH + U] = hcn;
            }
        } else {
            // replicate identical result to all 4 of this thread's rows
            #pragma unroll
            for (int ii = 0; ii < 4; ii++) {
                int mr = mBase + myRow + ii;
                long long ob = ((long long)mr * SLT + t) * 256;
                out[ob + U]       = hrn;
                out[ob + 128 + U] = hcn;
                hrow_out[mr * HH + U] = hrn;
                int ms = mr + NB; if (ms >= MM) ms -= MM;
                hcol_out[ms * HH + U] = hcn;
            }
            // hidden picks never fire for pre-start rows
        }
    }
}

// ---------------- launch ----------------
extern "C" void kernel_launch(void* const* d_in, const int* in_sizes, int n_in,
                              void* d_out, int out_size) {
    const float* input = (const float*)d_in[0];
    const float* Wf    = (const float*)d_in[1];
    const float* bf    = (const float*)d_in[2];
    const float* Wrm   = (const float*)d_in[3];
    const float* brm   = (const float*)d_in[4];
    const float* Wcm   = (const float*)d_in[5];
    const float* bcm   = (const float*)d_in[6];
    const float* Wrxm  = (const float*)d_in[7];
    const float* brxm  = (const float*)d_in[8];
    const float* Wcxm  = (const float*)d_in[9];
    const float* bcxm  = (const float*)d_in[10];
    float* out = (float*)d_out;

    long long need = (long long)MM * SLT * 256 + (long long)NB * SN * HH + (long long)NB * OLEN * HH;
    int write_hidden = ((long long)out_size >= need) ? 1 : 0;

    zero_all_kernel<<<256, 256>>>();
    prep_weights_kernel<<<NG, KK>>>(Wf, bf, Wrm, brm, Wcm, bcm, Wrxm, brxm, Wcxm, bcxm);

    dim3 grid(8, 48);
    for (int t = 0; t < SLT; ++t) {
        step_kernel<<<grid, 256>>>(input, out, t, t & 1, write_hidden);
    }
}

// round 7
// speedup vs baseline: 1.2430x; 1.1948x over previous
#include <cuda_runtime.h>
#include <cstdint>

// Problem constants
#define SN 96        // slices (ROW)
#define NB 32        // batch B
#define MM 3072      // SN*NB recurrent rows
#define OLEN 48      // COL (original slice len)
#define SLT 143      // SN + OLEN - 1 time steps
#define HH 128       // hidden
#define DD 32        // input feature dim
#define KK 288       // fused GEMM K = 2H + D
#define NG 768       // gate width = 6H

typedef unsigned long long ull;

// ---------------- device scratch ----------------
__device__ float g_W[KK * NG];      // fused, column-permuted weight [288][768]
__device__ float g_bias[NG];
__device__ float g_hrow[2][MM * HH];
__device__ float g_hcol[2][MM * HH];

// ---------------- helpers ----------------
__device__ __forceinline__ ull pack2(float x, float y) {
    ull r;
    asm("mov.b64 %0, {%1, %2};" : "=l"(r) : "f"(x), "f"(y));
    return r;
}
__device__ __forceinline__ void unpack2(ull v, float& x, float& y) {
    asm("mov.b64 {%0, %1}, %2;" : "=f"(x), "=f"(y) : "l"(v));
}
__device__ __forceinline__ void fma2(ull& acc, ull a, ull b) {
    asm("fma.rn.f32x2 %0, %1, %2, %0;" : "+l"(acc) : "l"(a), "l"(b));
}
__device__ __forceinline__ float tanh_ap(float x) {
    float y;
    asm("tanh.approx.f32 %0, %1;" : "=f"(y) : "f"(x));
    return y;
}
__device__ __forceinline__ float sigmoid_f(float x) {
    return fmaf(0.5f, tanh_ap(0.5f * x), 0.5f);
}

// ---------------- init ----------------
__global__ void zero_all_kernel() {
    int n = MM * HH;
    for (int i = blockIdx.x * blockDim.x + threadIdx.x; i < n; i += gridDim.x * blockDim.x) {
        g_hrow[0][i] = 0.f; g_hrow[1][i] = 0.f;
        g_hcol[0][i] = 0.f; g_hcol[1][i] = 0.f;
    }
}

// ---------------- prep: fused + permuted weights ----------------
// K layout: [0:128)=h_row, [128:256)=h_col, [256:288)=x
// col permutation: p = u*6 + g, original column oc = g*128 + u
//   g: 0=u_r 1=o_r 2=u_c 3=o_c 4=i_r 5=i_c
__global__ void prep_weights_kernel(
    const float* __restrict__ Wf,  const float* __restrict__ bf,
    const float* __restrict__ Wrm, const float* __restrict__ brm,
    const float* __restrict__ Wcm, const float* __restrict__ bcm,
    const float* __restrict__ Wrxm, const float* __restrict__ brxm,
    const float* __restrict__ Wcxm, const float* __restrict__ bcxm)
{
    int p = blockIdx.x;              // 0..767
    int u = p / 6, g = p % 6;
    int oc = g * 128 + u;

    __shared__ float sWf[KK];
    for (int i = threadIdx.x; i < KK; i += blockDim.x) sWf[i] = Wf[oc * KK + i];
    __syncthreads();

    int k = threadIdx.x;             // 288 threads
    if (k < KK) {
        float acc = 0.f;
        if (k < HH) {
            #pragma unroll 4
            for (int h = 0; h < HH; h++) acc += Wrm[h * HH + k] * sWf[h];
        } else if (k < 2 * HH) {
            int kk = k - HH;
            #pragma unroll 4
            for (int h = 0; h < HH; h++) acc += Wcm[h * HH + kk] * sWf[HH + h];
        } else {
            int d = k - 2 * HH;
            #pragma unroll 4
            for (int h = 0; h < HH; h++)
                acc += Wrxm[h * DD + d] * sWf[h] + Wcxm[h * DD + d] * sWf[HH + h];
            acc += sWf[2 * HH + d];
        }
        g_W[k * NG + p] = acc;
    }
    if (threadIdx.x == 0) {
        float bacc = bf[oc];
        for (int h = 0; h < HH; h++)
            bacc += (brxm[h] + brm[h]) * sWf[h] + (bcxm[h] + bcm[h]) * sWf[HH + h];
        g_bias[p] = bacc;
    }
}

// ---------------- per-step fused GEMM + gating ----------------
// grid: (8 n-tiles of 96, 48 m-tiles of 64), 256 threads.
// warp grid 4(row)x2(col), warp tile 16x48; lane grid 4x8, thread tile 4 rows x 6 cols
// (= exactly 1 hidden unit's 6 permuted gates per thread column group).
__global__ __launch_bounds__(256, 3) void step_kernel(
    const float* __restrict__ input,   // [B, SN, OLEN, D]
    float* __restrict__ out,
    int t, int pin, int write_hidden)
{
    __shared__ ull   sF2[64][33];  // feature tile [row][k], (v,v) duplicated pairs
    __shared__ float sW[32][96];   // weight tile [k][col]

    const float* __restrict__ hrow_in = g_hrow[pin];
    const float* __restrict__ hcol_in = g_hcol[pin];
    float* __restrict__ hrow_out = g_hrow[pin ^ 1];
    float* __restrict__ hcol_out = g_hcol[pin ^ 1];

    const int tid    = threadIdx.x;
    const int lane   = tid & 31;
    const int warp   = tid >> 5;
    const int warp_r = warp & 3;       // 0..3
    const int warp_c = warp >> 2;      // 0..1
    const int laneR  = lane >> 3;      // 0..3
    const int laneC  = lane & 7;       // 0..7
    const int mBase  = blockIdx.y * 64;
    const int nBase  = blockIdx.x * 96;

    // both slices of this block strictly pre-start -> all 64 rows share one state
    const bool dup = ((mBase >> 5) > t);

    const int myRow = warp_r * 16 + laneR * 4;     // local row of thread's first row
    const int myCol = warp_c * 48 + laneC * 6;     // local col of thread's 6 gate cols

    ull acc[4][3];
    #pragma unroll
    for (int i = 0; i < 4; i++)
        #pragma unroll
        for (int j = 0; j < 3; j++) acc[i][j] = 0ull;

    const int lk  = tid & 31;      // k within chunk
    const int lm0 = tid >> 5;      // 0..7

    for (int kc = 0; kc < 9; ++kc) {
        // --- load feature tile (64 rows x 32 k), store as (v,v) pairs ---
        int kg = kc * 32 + lk;
        #pragma unroll
        for (int mmi = 0; mmi < 8; ++mmi) {
            int ml = lm0 + mmi * 8;
            int m  = mBase + ml;
            float v;
            if (kc < 4) {
                v = hrow_in[m * HH + kg];
            } else if (kc < 8) {
                v = hcol_in[m * HH + (kg - HH)];
            } else {
                int r = m >> 5, b = m & 31;
                int c = t - r;
                v = (c >= 0 && c < OLEN)
                    ? input[(((b * SN) + r) * OLEN + c) * DD + (kg - 2 * HH)]
                    : 0.f;
            }
            sF2[ml][lk] = pack2(v, v);
        }
        // --- load weight tile (32 k x 96 cols) as float4 ---
        #pragma unroll
        for (int it = 0; it < 3; ++it) {
            int lin = tid + it * 256;     // 0..767 float4 slots
            int k   = lin / 24;
            int j4  = lin % 24;
            float4 w = *reinterpret_cast<const float4*>(&g_W[(kc * 32 + k) * NG + nBase + j4 * 4]);
            *reinterpret_cast<float4*>(&sW[k][j4 * 4]) = w;
        }
        __syncthreads();

        if (!dup) {
            #pragma unroll 8
            for (int k = 0; k < 32; ++k) {
                const ull* wp = reinterpret_cast<const ull*>(&sW[k][myCol]);
                ull w0 = wp[0], w1 = wp[1], w2 = wp[2];
                #pragma unroll
                for (int i = 0; i < 4; i++) {
                    ull f = sF2[myRow + i][k];
                    fma2(acc[i][0], f, w0);
                    fma2(acc[i][1], f, w1);
                    fma2(acc[i][2], f, w2);
                }
            }
        } else {
            // all rows identical: compute one row only
            #pragma unroll 8
            for (int k = 0; k < 32; ++k) {
                const ull* wp = reinterpret_cast<const ull*>(&sW[k][myCol]);
                ull w0 = wp[0], w1 = wp[1], w2 = wp[2];
                ull f = sF2[myRow][k];
                fma2(acc[0][0], f, w0);
                fma2(acc[0][1], f, w1);
                fma2(acc[0][2], f, w2);
            }
        }
        __syncthreads();
    }

    // --- epilogue: bias + gating + state update + outputs ---
    float bloc[6];
    #pragma unroll
    for (int j = 0; j < 6; j++) bloc[j] = g_bias[nBase + myCol + j];

    const int U = blockIdx.x * 16 + warp_c * 8 + laneC;   // global hidden unit

    const long long HR_BASE = (long long)MM * SLT * 256;
    const long long HC_BASE = HR_BASE + (long long)NB * SN * HH;

    const int nrows = dup ? 1 : 4;

    #pragma unroll 4
    for (int i = 0; i < nrows; i++) {
        int m = mBase + myRow + i;
        int r = m >> 5, b = m & 31;

        float a_ur, a_or, a_uc, a_oc, a_ir, a_ic;
        unpack2(acc[i][0], a_ur, a_or);
        unpack2(acc[i][1], a_uc, a_oc);
        unpack2(acc[i][2], a_ir, a_ic);
        a_ur += bloc[0]; a_or += bloc[1];
        a_uc += bloc[2]; a_oc += bloc[3];
        a_ir += bloc[4]; a_ic += bloc[5];

        float hr = hrow_in[m * HH + U];
        float hc = hcol_in[m * HH + U];

        float ur = sigmoid_f(a_ur);
        float og = sigmoid_f(a_or);
        float uc = sigmoid_f(a_uc);
        float oc = sigmoid_f(a_oc);
        float ir = tanh_ap(a_ir);
        float ic = tanh_ap(a_ic);

        float hrn = tanh_ap((1.f - ur) * hr + ur * ir) * og;
        float hcn = tanh_ap((1.f - uc) * hc + uc * ic) * oc;

        if (!dup) {
            long long ob = ((long long)m * SLT + t) * 256;
            out[ob + U]       = hrn;
            out[ob + 128 + U] = hcn;
            hrow_out[m * HH + U] = hrn;
            int ms = m + NB; if (ms >= MM) ms -= MM;   // roll(h_col, B)
            hcol_out[ms * HH + U] = hcn;

            if (write_hidden) {
                if (t - r == OLEN - 1)
                    out[HR_BASE + ((long long)b * SN + r) * HH + U] = hrn;
                if (r == SN - 1 && t >= SN - 1)
                    out[HC_BASE + ((long long)b * OLEN + (t - (SN - 1))) * HH + U] = hcn;
            }
        } else {
            // replicate identical result to all 4 rows of this thread
            #pragma unroll
            for (int ii = 0; ii < 4; ii++) {
                int mr = mBase + myRow + ii;
                long long ob = ((long long)mr * SLT + t) * 256;
                out[ob + U]       = hrn;
                out[ob + 128 + U] = hcn;
                hrow_out[mr * HH + U] = hrn;
                int ms = mr + NB; if (ms >= MM) ms -= MM;
                hcol_out[ms * HH + U] = hcn;
            }
            // hidden picks never fire for pre-start rows
        }
    }
}

// ---------------- launch ----------------
extern "C" void kernel_launch(void* const* d_in, const int* in_sizes, int n_in,
                              void* d_out, int out_size) {
    const float* input = (const float*)d_in[0];
    const float* Wf    = (const float*)d_in[1];
    const float* bf    = (const float*)d_in[2];
    const float* Wrm   = (const float*)d_in[3];
    const float* brm   = (const float*)d_in[4];
    const float* Wcm   = (const float*)d_in[5];
    const float* bcm   = (const float*)d_in[6];
    const float* Wrxm  = (const float*)d_in[7];
    const float* brxm  = (const float*)d_in[8];
    const float* Wcxm  = (const float*)d_in[9];
    const float* bcxm  = (const float*)d_in[10];
    float* out = (float*)d_out;

    long long need = (long long)MM * SLT * 256 + (long long)NB * SN * HH + (long long)NB * OLEN * HH;
    int write_hidden = ((long long)out_size >= need) ? 1 : 0;

    zero_all_kernel<<<256, 256>>>();
    prep_weights_kernel<<<NG, KK>>>(Wf, bf, Wrm, brm, Wcm, bcm, Wrxm, brxm, Wcxm, bcxm);

    dim3 grid(8, 48);
    for (int t = 0; t < SLT; ++t) {
        step_kernel<<<grid, 256>>>(input, out, t, t & 1, write_hidden);
    }
}

// round 8
// speedup vs baseline: 1.4656x; 1.1790x over previous
#include <cuda_runtime.h>
#include <cstdint>

// Problem constants
#define SN 96        // slices (ROW)
#define NB 32        // batch B
#define MM 3072      // SN*NB recurrent rows
#define OLEN 48      // COL (original slice len)
#define SLT 143      // SN + OLEN - 1 time steps
#define HH 128       // hidden
#define DD 32        // input feature dim
#define KK 288       // fused GEMM K = 2H + D
#define NG 768       // gate width = 6H

typedef unsigned long long ull;

// ---------------- device scratch ----------------
__device__ float g_W[KK * NG];      // fused, column-permuted weight [288][768]
__device__ float g_bias[NG];
__device__ float g_hrow[2][MM * HH];
__device__ float g_hcol[2][MM * HH];

// ---------------- helpers ----------------
__device__ __forceinline__ ull pack2(float x, float y) {
    ull r;
    asm("mov.b64 %0, {%1, %2};" : "=l"(r) : "f"(x), "f"(y));
    return r;
}
__device__ __forceinline__ void unpack2(ull v, float& x, float& y) {
    asm("mov.b64 {%0, %1}, %2;" : "=f"(x), "=f"(y) : "l"(v));
}
__device__ __forceinline__ void fma2(ull& acc, ull a, ull b) {
    asm("fma.rn.f32x2 %0, %1, %2, %0;" : "+l"(acc) : "l"(a), "l"(b));
}
__device__ __forceinline__ float tanh_ap(float x) {
    float y;
    asm("tanh.approx.f32 %0, %1;" : "=f"(y) : "f"(x));
    return y;
}
__device__ __forceinline__ float sigmoid_f(float x) {
    return fmaf(0.5f, tanh_ap(0.5f * x), 0.5f);
}

// ---------------- init ----------------
__global__ void zero_all_kernel() {
    int n = MM * HH;
    for (int i = blockIdx.x * blockDim.x + threadIdx.x; i < n; i += gridDim.x * blockDim.x) {
        g_hrow[0][i] = 0.f; g_hrow[1][i] = 0.f;
        g_hcol[0][i] = 0.f; g_hcol[1][i] = 0.f;
    }
}

// ---------------- prep: fused + permuted weights ----------------
// K layout: [0:128)=h_row, [128:256)=h_col, [256:288)=x
// col permutation: p = u*6 + g, original column oc = g*128 + u
//   g: 0=u_r 1=o_r 2=u_c 3=o_c 4=i_r 5=i_c
__global__ void prep_weights_kernel(
    const float* __restrict__ Wf,  const float* __restrict__ bf,
    const float* __restrict__ Wrm, const float* __restrict__ brm,
    const float* __restrict__ Wcm, const float* __restrict__ bcm,
    const float* __restrict__ Wrxm, const float* __restrict__ brxm,
    const float* __restrict__ Wcxm, const float* __restrict__ bcxm)
{
    int p = blockIdx.x;              // 0..767
    int u = p / 6, g = p % 6;
    int oc = g * 128 + u;

    __shared__ float sWf[KK];
    for (int i = threadIdx.x; i < KK; i += blockDim.x) sWf[i] = Wf[oc * KK + i];
    __syncthreads();

    int k = threadIdx.x;             // 288 threads
    if (k < KK) {
        float acc = 0.f;
        if (k < HH) {
            #pragma unroll 4
            for (int h = 0; h < HH; h++) acc += Wrm[h * HH + k] * sWf[h];
        } else if (k < 2 * HH) {
            int kk = k - HH;
            #pragma unroll 4
            for (int h = 0; h < HH; h++) acc += Wcm[h * HH + kk] * sWf[HH + h];
        } else {
            int d = k - 2 * HH;
            #pragma unroll 4
            for (int h = 0; h < HH; h++)
                acc += Wrxm[h * DD + d] * sWf[h] + Wcxm[h * DD + d] * sWf[HH + h];
            acc += sWf[2 * HH + d];
        }
        g_W[k * NG + p] = acc;
    }
    if (threadIdx.x == 0) {
        float bacc = bf[oc];
        for (int h = 0; h < HH; h++)
            bacc += (brxm[h] + brm[h]) * sWf[h] + (bcxm[h] + bcm[h]) * sWf[HH + h];
        g_bias[p] = bacc;
    }
}

// ---------------- per-step fused GEMM + gating ----------------
// grid: (4 n-tiles of 192, 32 m-tiles of 96) = 128 blocks (single wave), 512 threads.
// warp grid 4(row)x4(col); lanes 4(row)x8(col); thread tile 6 rows x 6 cols (1 unit).
// Double-buffered SMEM chunks, register prefetch, 1 sync per chunk.

// dynamic smem layout (floats):
//   sF: 2 bufs x [96][33]   offset 0
//   sW: 2 bufs x [32][196]  offset 2*96*33 = 6336
#define SF_OFF(buf, row, k)  ((buf) * (96 * 33) + (row) * 33 + (k))
#define SW_OFF(buf, k, col)  (6336 + (buf) * (32 * 196) + (k) * 196 + (col))
#define SMEM_FLOATS (6336 + 2 * 32 * 196)

__device__ __forceinline__ void load_feat(
    const float* __restrict__ hrow_in, const float* __restrict__ hcol_in,
    const float* __restrict__ input,
    int kc, int t, int mBase, int tid, bool dup, float* dst)
{
    if (!dup) {
        #pragma unroll
        for (int it = 0; it < 6; ++it) {
            int lin = tid + it * 512;      // 0..3071
            int row = lin >> 5, k = lin & 31;
            int m = mBase + row;
            float v;
            if (kc < 4) {
                v = hrow_in[m * HH + kc * 32 + k];
            } else if (kc < 8) {
                v = hcol_in[m * HH + (kc - 4) * 32 + k];
            } else {
                int r = m >> 5, b = m & 31;
                int c = t - r;
                v = (c >= 0 && c < OLEN)
                    ? input[((b * SN + r) * OLEN + c) * DD + k]
                    : 0.f;
            }
            dst[it] = v;
        }
    } else if (tid < 32) {
        // universal pre-start trajectory: row 0 only; x is always 0 pre-start
        int k = tid;
        float v;
        if (kc < 4)      v = hrow_in[mBase * HH + kc * 32 + k];
        else if (kc < 8) v = hcol_in[mBase * HH + (kc - 4) * 32 + k];
        else             v = 0.f;
        dst[0] = v;
    }
}

__device__ __forceinline__ void load_wt(int kc, int nBase, int tid, float4* dst)
{
    #pragma unroll
    for (int it = 0; it < 3; ++it) {
        int lin = tid + it * 512;          // 0..1535
        int k = lin / 48, j4 = lin % 48;
        dst[it] = *reinterpret_cast<const float4*>(&g_W[(kc * 32 + k) * NG + nBase + j4 * 4]);
    }
}

__global__ __launch_bounds__(512, 1) void step_kernel(
    const float* __restrict__ input,   // [B, SN, OLEN, D]
    float* __restrict__ out,
    int t, int pin, int write_hidden)
{
    extern __shared__ float smem[];

    const float* __restrict__ hrow_in = g_hrow[pin];
    const float* __restrict__ hcol_in = g_hcol[pin];
    float* __restrict__ hrow_out = g_hrow[pin ^ 1];
    float* __restrict__ hcol_out = g_hcol[pin ^ 1];

    const int tid    = threadIdx.x;
    const int lane   = tid & 31;
    const int warp   = tid >> 5;
    const int warp_r = warp & 3;        // 0..3
    const int warp_c = warp >> 2;       // 0..3
    const int laneR  = lane >> 3;       // 0..3
    const int laneC  = lane & 7;        // 0..7
    const int mBase  = blockIdx.y * 96;
    const int nBase  = blockIdx.x * 192;

    const int myRow = warp_r * 24 + laneR * 6;          // 0..90
    const int myCol = (warp_c * 8 + laneC) * 6;         // 0..186

    // all 3 slices of this block strictly pre-start -> single shared trajectory
    const bool dup = (3 * (int)blockIdx.y > t);

    ull acc[6][3];
    #pragma unroll
    for (int i = 0; i < 6; i++)
        #pragma unroll
        for (int j = 0; j < 3; j++) acc[i][j] = 0ull;

    float  pfF[6];
    float4 pfW[3];

    // ---- prologue: fetch + stage chunk 0 ----
    load_feat(hrow_in, hcol_in, input, 0, t, mBase, tid, dup, pfF);
    load_wt(0, nBase, tid, pfW);
    if (!dup) {
        #pragma unroll
        for (int it = 0; it < 6; ++it) {
            int lin = tid + it * 512;
            smem[SF_OFF(0, lin >> 5, lin & 31)] = pfF[it];
        }
    } else if (tid < 32) {
        smem[SF_OFF(0, 0, tid)] = pfF[0];
    }
    #pragma unroll
    for (int it = 0; it < 3; ++it) {
        int lin = tid + it * 512;
        int k = lin / 48, j4 = lin % 48;
        *reinterpret_cast<float4*>(&smem[SW_OFF(0, k, j4 * 4)]) = pfW[it];
    }
    __syncthreads();

    for (int kc = 0; kc < 9; ++kc) {
        const int cur = kc & 1;

        // ---- prefetch next chunk into registers (overlaps compute) ----
        if (kc < 8) {
            load_feat(hrow_in, hcol_in, input, kc + 1, t, mBase, tid, dup, pfF);
            load_wt(kc + 1, nBase, tid, pfW);
        }

        // ---- compute current chunk ----
        if (!dup) {
            #pragma unroll 4
            for (int k = 0; k < 32; ++k) {
                const ull* wp = reinterpret_cast<const ull*>(&smem[SW_OFF(cur, k, myCol)]);
                ull w0 = wp[0], w1 = wp[1], w2 = wp[2];
                #pragma unroll
                for (int i = 0; i < 6; i++) {
                    float fv = smem[SF_OFF(cur, myRow + i, k)];
                    ull f = pack2(fv, fv);
                    fma2(acc[i][0], f, w0);
                    fma2(acc[i][1], f, w1);
                    fma2(acc[i][2], f, w2);
                }
            }
        } else {
            #pragma unroll 4
            for (int k = 0; k < 32; ++k) {
                const ull* wp = reinterpret_cast<const ull*>(&smem[SW_OFF(cur, k, myCol)]);
                ull w0 = wp[0], w1 = wp[1], w2 = wp[2];
                float fv = smem[SF_OFF(cur, 0, k)];
                ull f = pack2(fv, fv);
                fma2(acc[0][0], f, w0);
                fma2(acc[0][1], f, w1);
                fma2(acc[0][2], f, w2);
            }
        }

        // ---- stage next chunk into alternate buffer; single barrier ----
        if (kc < 8) {
            const int nxt = cur ^ 1;
            if (!dup) {
                #pragma unroll
                for (int it = 0; it < 6; ++it) {
                    int lin = tid + it * 512;
                    smem[SF_OFF(nxt, lin >> 5, lin & 31)] = pfF[it];
                }
            } else if (tid < 32) {
                smem[SF_OFF(nxt, 0, tid)] = pfF[0];
            }
            #pragma unroll
            for (int it = 0; it < 3; ++it) {
                int lin = tid + it * 512;
                int k = lin / 48, j4 = lin % 48;
                *reinterpret_cast<float4*>(&smem[SW_OFF(nxt, k, j4 * 4)]) = pfW[it];
            }
            __syncthreads();
        }
    }

    // ---- epilogue: bias + gating + state update + outputs ----
    float bloc[6];
    #pragma unroll
    for (int j = 0; j < 6; j++) bloc[j] = g_bias[nBase + myCol + j];

    const int U = blockIdx.x * 32 + warp_c * 8 + laneC;   // global hidden unit

    const long long HR_BASE = (long long)MM * SLT * 256;
    const long long HC_BASE = HR_BASE + (long long)NB * SN * HH;

    const int nrows = dup ? 1 : 6;

    for (int i = 0; i < nrows; i++) {
        int m = mBase + myRow + i;
        if (dup) m = mBase;               // universal row
        int r = m >> 5, b = m & 31;

        float a_ur, a_or, a_uc, a_oc, a_ir, a_ic;
        unpack2(acc[i][0], a_ur, a_or);
        unpack2(acc[i][1], a_uc, a_oc);
        unpack2(acc[i][2], a_ir, a_ic);
        a_ur += bloc[0]; a_or += bloc[1];
        a_uc += bloc[2]; a_oc += bloc[3];
        a_ir += bloc[4]; a_ic += bloc[5];

        float hr = hrow_in[m * HH + U];
        float hc = hcol_in[m * HH + U];

        float ur = sigmoid_f(a_ur);
        float og = sigmoid_f(a_or);
        float uc = sigmoid_f(a_uc);
        float oc = sigmoid_f(a_oc);
        float ir = tanh_ap(a_ir);
        float ic = tanh_ap(a_ic);

        float hrn = tanh_ap((1.f - ur) * hr + ur * ir) * og;
        float hcn = tanh_ap((1.f - uc) * hc + uc * ic) * oc;

        if (!dup) {
            long long ob = ((long long)m * SLT + t) * 256;
            out[ob + U]       = hrn;
            out[ob + 128 + U] = hcn;
            hrow_out[m * HH + U] = hrn;
            int ms = m + NB; if (ms >= MM) ms -= MM;   // roll(h_col, B)
            hcol_out[ms * HH + U] = hcn;

            if (write_hidden) {
                if (t - r == OLEN - 1)
                    out[HR_BASE + ((long long)b * SN + r) * HH + U] = hrn;
                if (r == SN - 1 && t >= SN - 1)
                    out[HC_BASE + ((long long)b * OLEN + (t - (SN - 1))) * HH + U] = hcn;
            }
        } else {
            // replicate identical result to this thread's 6 rows
            #pragma unroll
            for (int ii = 0; ii < 6; ii++) {
                int mr = mBase + myRow + ii;
                long long ob = ((long long)mr * SLT + t) * 256;
                out[ob + U]       = hrn;
                out[ob + 128 + U] = hcn;
                hrow_out[mr * HH + U] = hrn;
                int ms = mr + NB; if (ms >= MM) ms -= MM;
                hcol_out[ms * HH + U] = hcn;
            }
            // hidden picks never fire for pre-start rows
        }
    }
}

// ---------------- launch ----------------
extern "C" void kernel_launch(void* const* d_in, const int* in_sizes, int n_in,
                              void* d_out, int out_size) {
    const float* input = (const float*)d_in[0];
    const float* Wf    = (const float*)d_in[1];
    const float* bf    = (const float*)d_in[2];
    const float* Wrm   = (const float*)d_in[3];
    const float* brm   = (const float*)d_in[4];
    const float* Wcm   = (const float*)d_in[5];
    const float* bcm   = (const float*)d_in[6];
    const float* Wrxm  = (const float*)d_in[7];
    const float* brxm  = (const float*)d_in[8];
    const float* Wcxm  = (const float*)d_in[9];
    const float* bcxm  = (const float*)d_in[10];
    float* out = (float*)d_out;

    long long need = (long long)MM * SLT * 256 + (long long)NB * SN * HH + (long long)NB * OLEN * HH;
    int write_hidden = ((long long)out_size >= need) ? 1 : 0;

    size_t smem_bytes = (size_t)SMEM_FLOATS * sizeof(float);   // ~75.5 KB
    static int smem_set = 0;
    if (!smem_set) {
        cudaFuncSetAttribute(step_kernel, cudaFuncAttributeMaxDynamicSharedMemorySize,
                             (int)smem_bytes);
        smem_set = 1;
    }

    zero_all_kernel<<<256, 256>>>();
    prep_weights_kernel<<<NG, KK>>>(Wf, bf, Wrm, brm, Wcm, bcm, Wrxm, brxm, Wcxm, bcxm);

    dim3 grid(4, 32);
    for (int t = 0; t < SLT; ++t) {
        step_kernel<<<grid, 512, smem_bytes>>>(input, out, t, t & 1, write_hidden);
    }
}

// round 10
// speedup vs baseline: 1.6790x; 1.1456x over previous
#include <cuda_runtime.h>
#include <cuda_bf16.h>
#include <cstdint>

// Problem constants
#define SN 96
#define NB 32
#define MM 3072
#define OLEN 48
#define SLT 143
#define HH 128
#define DD 32
#define KK 288       // fused K = 2H + D
#define NG 768       // 6H gate cols
#define NX (NB * SN * OLEN * DD)

#define MT 128       // block M tile
#define NT 192       // block N tile
#define ARS 80       // smem row stride bytes (32 bf16 + 16B pad)
#define ABUF (128 * ARS)     // 10240
#define BBUF (192 * ARS)     // 15360
#define OFF_A 0
#define OFF_B (2 * ABUF)     // 20480
#define SMEM_BYTES (2 * ABUF + 2 * BBUF)   // 51200

// ---------------- device scratch ----------------
__device__ __nv_bfloat16 g_Wh[NG * KK];
__device__ __nv_bfloat16 g_Wl[NG * KK];
__device__ float g_bias[NG];
__device__ float g_hrow[2][MM * HH];
__device__ float g_hcol[2][MM * HH];
__device__ __nv_bfloat16 g_hr_h[2][MM * HH], g_hr_l[2][MM * HH];
__device__ __nv_bfloat16 g_hc_h[2][MM * HH], g_hc_l[2][MM * HH];
__device__ __nv_bfloat16 g_x_h[NX], g_x_l[NX];

// ---------------- helpers ----------------
__device__ __forceinline__ uint32_t smem_u32(const void* p) {
    uint32_t a;
    asm("{ .reg .u64 t; cvta.to.shared.u64 t, %1; cvt.u32.u64 %0, t; }" : "=r"(a) : "l"(p));
    return a;
}
__device__ __forceinline__ void ldsm_x4(uint32_t& r0, uint32_t& r1, uint32_t& r2, uint32_t& r3,
                                        uint32_t addr) {
    asm volatile("ldmatrix.sync.aligned.m8n8.x4.shared.b16 {%0,%1,%2,%3}, [%4];"
                 : "=r"(r0), "=r"(r1), "=r"(r2), "=r"(r3) : "r"(addr));
}
__device__ __forceinline__ void mma16816(float* c, uint32_t a0, uint32_t a1, uint32_t a2,
                                         uint32_t a3, uint32_t b0, uint32_t b1) {
    asm volatile(
        "mma.sync.aligned.m16n8k16.row.col.f32.bf16.bf16.f32 "
        "{%0,%1,%2,%3}, {%4,%5,%6,%7}, {%8,%9}, {%0,%1,%2,%3};"
        : "+f"(c[0]), "+f"(c[1]), "+f"(c[2]), "+f"(c[3])
        : "r"(a0), "r"(a1), "r"(a2), "r"(a3), "r"(b0), "r"(b1));
}
__device__ __forceinline__ float tanh_ap(float x) {
    float y;
    asm("tanh.approx.f32 %0, %1;" : "=f"(y) : "f"(x));
    return y;
}
__device__ __forceinline__ float sigmoid_f(float x) {
    return fmaf(0.5f, tanh_ap(0.5f * x), 0.5f);
}

// ---------------- init ----------------
__global__ void zero_all_kernel() {
    const __nv_bfloat16 bz = __float2bfloat16(0.f);
    int n = MM * HH;
    for (int i = blockIdx.x * blockDim.x + threadIdx.x; i < n; i += gridDim.x * blockDim.x) {
        g_hrow[0][i] = 0.f; g_hrow[1][i] = 0.f;
        g_hcol[0][i] = 0.f; g_hcol[1][i] = 0.f;
        g_hr_h[0][i] = bz; g_hr_h[1][i] = bz;
        g_hr_l[0][i] = bz; g_hr_l[1][i] = bz;
        g_hc_h[0][i] = bz; g_hc_h[1][i] = bz;
        g_hc_l[0][i] = bz; g_hc_l[1][i] = bz;
    }
}

__global__ void prep_x_kernel(const float* __restrict__ input) {
    for (int i = blockIdx.x * blockDim.x + threadIdx.x; i < NX; i += gridDim.x * blockDim.x) {
        float v = input[i];
        __nv_bfloat16 hi = __float2bfloat16(v);
        g_x_h[i] = hi;
        g_x_l[i] = __float2bfloat16(v - __bfloat162float(hi));
    }
}

// ---------------- prep: fused weights, mma-epilogue column permutation ----------------
// col position cp -> (unit u, pairtype p, elem e):
//   nb=cp/192, rem=cp%192, wN=rem/48, r2=rem%48, tile=r2/8, c=(r2%8)/2, e=r2&1
//   p=tile%3, q=tile/3, u=nb*32+wN*8+q*4+c, original gate g=p*2+e, oc=g*128+u
// K layout: [0:128)=h_row, [128:256)=h_col, [256:288)=x
__global__ void prep_weights_kernel(
    const float* __restrict__ Wf,  const float* __restrict__ bf,
    const float* __restrict__ Wrm, const float* __restrict__ brm,
    const float* __restrict__ Wcm, const float* __restrict__ bcm,
    const float* __restrict__ Wrxm, const float* __restrict__ brxm,
    const float* __restrict__ Wcxm, const float* __restrict__ bcxm)
{
    int cp = blockIdx.x;              // 0..767
    int nb = cp / 192, rem = cp % 192;
    int wN = rem / 48, r2 = rem % 48;
    int tile = r2 >> 3, ce = r2 & 7;
    int c = ce >> 1, e = ce & 1;
    int p = tile % 3, q = tile / 3;
    int u = nb * 32 + wN * 8 + q * 4 + c;
    int oc = (p * 2 + e) * 128 + u;

    __shared__ float sWf[KK];
    for (int i = threadIdx.x; i < KK; i += blockDim.x) sWf[i] = Wf[oc * KK + i];
    __syncthreads();

    int k = threadIdx.x;             // 288 threads
    float acc = 0.f;
    if (k < HH) {
        #pragma unroll 4
        for (int h = 0; h < HH; h++) acc += Wrm[h * HH + k] * sWf[h];
    } else if (k < 2 * HH) {
        int kk = k - HH;
        #pragma unroll 4
        for (int h = 0; h < HH; h++) acc += Wcm[h * HH + kk] * sWf[HH + h];
    } else {
        int d = k - 2 * HH;
        #pragma unroll 4
        for (int h = 0; h < HH; h++)
            acc += Wrxm[h * DD + d] * sWf[h] + Wcxm[h * DD + d] * sWf[HH + h];
        acc += sWf[2 * HH + d];
    }
    __nv_bfloat16 hi = __float2bfloat16(acc);
    g_Wh[cp * KK + k] = hi;
    g_Wl[cp * KK + k] = __float2bfloat16(acc - __bfloat162float(hi));

    if (threadIdx.x == 0) {
        float bacc = bf[oc];
        for (int h = 0; h < HH; h++)
            bacc += (brxm[h] + brm[h]) * sWf[h] + (bcxm[h] + bcm[h]) * sWf[HH + h];
        g_bias[cp] = bacc;
    }
}

// ---------------- staging fetchers ----------------
// extended-K schedule: cc = pass*9 + kc; pass0: Ah.Wh, pass1: Al.Wh, pass2: Ah.Wl
__device__ __forceinline__ uint4 fetchA(int cc, int tid, int mBase, int t, int pin) {
    int p = cc / 9, kc = cc - p * 9;
    int row = tid >> 2, slot = tid & 3;
    int m = mBase + row;
    if (kc < 8) {
        bool isRow = kc < 4;
        int kk = (isRow ? kc : kc - 4) * 32 + slot * 8;
        const __nv_bfloat16* src = isRow ? ((p == 1) ? g_hr_l[pin] : g_hr_h[pin])
                                         : ((p == 1) ? g_hc_l[pin] : g_hc_h[pin]);
        return *reinterpret_cast<const uint4*>(&src[m * HH + kk]);
    }
    int r = m >> 5, b = m & 31;
    int c = t - r;
    if (c >= 0 && c < OLEN) {
        const __nv_bfloat16* src = (p == 1) ? g_x_l : g_x_h;
        return *reinterpret_cast<const uint4*>(&src[((b * SN + r) * OLEN + c) * DD + slot * 8]);
    }
    return make_uint4(0u, 0u, 0u, 0u);
}
__device__ __forceinline__ uint4 fetchB(int cc, int lin, int nBase) {
    int p = cc / 9, kc = cc - p * 9;
    int row = lin >> 2, slot = lin & 3;
    const __nv_bfloat16* w = (p == 2) ? g_Wl : g_Wh;
    return *reinterpret_cast<const uint4*>(&w[(nBase + row) * KK + kc * 32 + slot * 8]);
}

// ---------------- per-step: HMMA GEMM + gating ----------------
// grid (4 n-tiles of 192, 24 m-tiles of 128), 512 threads = 16 warps (4M x 4N),
// warp tile 32x48 (2 m16-tiles x 6 n8-tiles). K' = 864, 27 chunks of 32.
__global__ __launch_bounds__(512, 1) void step_kernel(
    float* __restrict__ out, int t, int pin, int write_hidden)
{
    extern __shared__ __align__(16) char sm[];
    const uint32_t sb = smem_u32(sm);

    const int tid   = threadIdx.x;
    const int lane  = tid & 31;
    const int wid   = tid >> 5;
    const int warpM = wid & 3;
    const int warpN = wid >> 2;
    const int mBase = blockIdx.y * MT;
    const int nBase = blockIdx.x * NT;

    const int g4 = lane >> 2, c4 = lane & 3;
    const int grp = lane >> 3, lr = lane & 7;

    // ldmatrix lane base addresses (exclude buf/mt/pair/ks terms)
    const uint32_t aBase = sb + OFF_A + (warpM * 32 + ((grp & 1) << 3) + lr) * ARS + ((grp >> 1) << 4);
    const uint32_t bBase = sb + OFF_B + (warpN * 48 + ((grp >> 1) << 3) + lr) * ARS + ((grp & 1) << 4);

    float acc[2][6][4];
    #pragma unroll
    for (int i = 0; i < 2; i++)
        #pragma unroll
        for (int j = 0; j < 6; j++)
            #pragma unroll
            for (int e = 0; e < 4; e++) acc[i][j][e] = 0.f;

    const int rowA = tid >> 2, slotA = tid & 3;

    // ---- prologue: stage chunk 0 into buffer 0 ----
    {
        uint4 a = fetchA(0, tid, mBase, t, pin);
        uint4 b0 = fetchB(0, tid, nBase);
        *reinterpret_cast<uint4*>(sm + OFF_A + rowA * ARS + slotA * 16) = a;
        *reinterpret_cast<uint4*>(sm + OFF_B + rowA * ARS + slotA * 16) = b0;
        if (tid < 256) {
            uint4 b1 = fetchB(0, 512 + tid, nBase);
            int lin = 512 + tid;
            *reinterpret_cast<uint4*>(sm + OFF_B + (lin >> 2) * ARS + (lin & 3) * 16) = b1;
        }
    }
    __syncthreads();

    for (int cc = 0; cc < 27; ++cc) {
        const int cur = cc & 1;

        // prefetch next chunk into registers
        uint4 pA, pB0, pB1;
        if (cc < 26) {
            pA  = fetchA(cc + 1, tid, mBase, t, pin);
            pB0 = fetchB(cc + 1, tid, nBase);
            if (tid < 256) pB1 = fetchB(cc + 1, 512 + tid, nBase);
        }

        // compute current chunk: 2 k16 steps
        const uint32_t aB = aBase + cur * ABUF;
        const uint32_t bB = bBase + cur * BBUF;
        #pragma unroll
        for (int ks = 0; ks < 2; ++ks) {
            uint32_t a[2][4];
            #pragma unroll
            for (int mt = 0; mt < 2; ++mt)
                ldsm_x4(a[mt][0], a[mt][1], a[mt][2], a[mt][3],
                        aB + mt * (16 * ARS) + ks * 32);
            uint32_t bt[6][2];
            #pragma unroll
            for (int pr = 0; pr < 3; ++pr) {
                uint32_t r0, r1, r2, r3;
                ldsm_x4(r0, r1, r2, r3, bB + pr * (16 * ARS) + ks * 32);
                bt[2 * pr][0] = r0; bt[2 * pr][1] = r1;
                bt[2 * pr + 1][0] = r2; bt[2 * pr + 1][1] = r3;
            }
            #pragma unroll
            for (int mt = 0; mt < 2; ++mt)
                #pragma unroll
                for (int nt = 0; nt < 6; ++nt)
                    mma16816(acc[mt][nt], a[mt][0], a[mt][1], a[mt][2], a[mt][3],
                             bt[nt][0], bt[nt][1]);
        }

        // stage next chunk into alternate buffer; single barrier
        if (cc < 26) {
            const int nxt = cur ^ 1;
            *reinterpret_cast<uint4*>(sm + OFF_A + nxt * ABUF + rowA * ARS + slotA * 16) = pA;
            *reinterpret_cast<uint4*>(sm + OFF_B + nxt * BBUF + rowA * ARS + slotA * 16) = pB0;
            if (tid < 256) {
                int lin = 512 + tid;
                *reinterpret_cast<uint4*>(sm + OFF_B + nxt * BBUF + (lin >> 2) * ARS + (lin & 3) * 16) = pB1;
            }
            __syncthreads();
        }
    }

    // ---- epilogue: bias + gating + state update + outputs ----
    const float* __restrict__ hrow_in = g_hrow[pin];
    const float* __restrict__ hcol_in = g_hcol[pin];
    float* __restrict__ hrow_out = g_hrow[pin ^ 1];
    float* __restrict__ hcol_out = g_hcol[pin ^ 1];
    __nv_bfloat16* __restrict__ hr_h_out = g_hr_h[pin ^ 1];
    __nv_bfloat16* __restrict__ hr_l_out = g_hr_l[pin ^ 1];
    __nv_bfloat16* __restrict__ hc_h_out = g_hc_h[pin ^ 1];
    __nv_bfloat16* __restrict__ hc_l_out = g_hc_l[pin ^ 1];

    float bl[2][3][2];
    #pragma unroll
    for (int q = 0; q < 2; ++q)
        #pragma unroll
        for (int p = 0; p < 3; ++p)
            #pragma unroll
            for (int e = 0; e < 2; ++e)
                bl[q][p][e] = g_bias[nBase + warpN * 48 + (q * 3 + p) * 8 + c4 * 2 + e];

    const long long HR_BASE = (long long)MM * SLT * 256;
    const long long HC_BASE = HR_BASE + (long long)NB * SN * HH;

    #pragma unroll
    for (int mt = 0; mt < 2; ++mt) {
        #pragma unroll
        for (int h = 0; h < 2; ++h) {
            const int m = mBase + warpM * 32 + mt * 16 + h * 8 + g4;
            const int r = m >> 5, b = m & 31;
            int ms = m + NB; if (ms >= MM) ms -= MM;
            const long long ob = ((long long)m * SLT + t) * 256;
            #pragma unroll
            for (int q = 0; q < 2; ++q) {
                const int U = blockIdx.x * 32 + warpN * 8 + q * 4 + c4;

                float a_ur = acc[mt][q * 3 + 0][h * 2 + 0] + bl[q][0][0];
                float a_or = acc[mt][q * 3 + 0][h * 2 + 1] + bl[q][0][1];
                float a_uc = acc[mt][q * 3 + 1][h * 2 + 0] + bl[q][1][0];
                float a_oc = acc[mt][q * 3 + 1][h * 2 + 1] + bl[q][1][1];
                float a_ir = acc[mt][q * 3 + 2][h * 2 + 0] + bl[q][2][0];
                float a_ic = acc[mt][q * 3 + 2][h * 2 + 1] + bl[q][2][1];

                float hr = hrow_in[m * HH + U];
                float hc = hcol_in[m * HH + U];

                float ur = sigmoid_f(a_ur);
                float og = sigmoid_f(a_or);
                float uc = sigmoid_f(a_uc);
                float oc = sigmoid_f(a_oc);
                float ir = tanh_ap(a_ir);
                float ic = tanh_ap(a_ic);

                float hrn = tanh_ap((1.f - ur) * hr + ur * ir) * og;
                float hcn = tanh_ap((1.f - uc) * hc + uc * ic) * oc;

                out[ob + U]       = hrn;
                out[ob + 128 + U] = hcn;

                hrow_out[m * HH + U] = hrn;
                hcol_out[ms * HH + U] = hcn;

                __nv_bfloat16 rh = __float2bfloat16(hrn);
                hr_h_out[m * HH + U] = rh;
                hr_l_out[m * HH + U] = __float2bfloat16(hrn - __bfloat162float(rh));
                __nv_bfloat16 ch = __float2bfloat16(hcn);
                hc_h_out[ms * HH + U] = ch;
                hc_l_out[ms * HH + U] = __float2bfloat16(hcn - __bfloat162float(ch));

                if (write_hidden) {
                    if (t - r == OLEN - 1)
                        out[HR_BASE + ((long long)b * SN + r) * HH + U] = hrn;
                    if (r == SN - 1 && t >= SN - 1)
                        out[HC_BASE + ((long long)b * OLEN + (t - (SN - 1))) * HH + U] = hcn;
                }
            }
        }
    }
}

// ---------------- launch ----------------
extern "C" void kernel_launch(void* const* d_in, const int* in_sizes, int n_in,
                              void* d_out, int out_size) {
    const float* input = (const float*)d_in[0];
    const float* Wf    = (const float*)d_in[1];
    const float* bf    = (const float*)d_in[2];
    const float* Wrm   = (const float*)d_in[3];
    const float* brm   = (const float*)d_in[4];
    const float* Wcm   = (const float*)d_in[5];
    const float* bcm   = (const float*)d_in[6];
    const float* Wrxm  = (const float*)d_in[7];
    const float* brxm  = (const float*)d_in[8];
    const float* Wcxm  = (const float*)d_in[9];
    const float* bcxm  = (const float*)d_in[10];
    float* out = (float*)d_out;

    long long need = (long long)MM * SLT * 256 + (long long)NB * SN * HH + (long long)NB * OLEN * HH;
    int write_hidden = ((long long)out_size >= need) ? 1 : 0;

    static int attr_set = 0;
    if (!attr_set) {
        cudaFuncSetAttribute(step_kernel, cudaFuncAttributeMaxDynamicSharedMemorySize,
                             SMEM_BYTES);
        attr_set = 1;
    }

    zero_all_kernel<<<256, 256>>>();
    prep_x_kernel<<<256, 256>>>(input);
    prep_weights_kernel<<<NG, KK>>>(Wf, bf, Wrm, brm, Wcm, bcm, Wrxm, brxm, Wcxm, bcxm);

    dim3 grid(4, 24);
    for (int t = 0; t < SLT; ++t) {
        step_kernel<<<grid, 512, SMEM_BYTES>>>(out, t, t & 1, write_hidden);
    }
}